// round 16
// baseline (speedup 1.0000x reference)
#include <cuda_runtime.h>
#include <cuda_bf16.h>
#include <cstdint>

#define DD 512
#define MAXN 200000
#define TAU_INV 2.0f
#define EPS 1e-8f

// ---------------- device scratch (no allocations allowed) ----------------
__device__ __align__(256) __nv_bfloat16 g_zbf[(size_t)MAXN * DD];  // z bf16
__device__ __align__(256) __nv_bfloat16 g_wbf[DD * DD];            // W bf16
__device__ float g_s[MAXN];                          // row sumsq of z (fp32)
__device__ float g_d2[MAXN];
__device__ float g_dot[MAXN];                        // z . v
__device__ float g_nsq[MAXN];                        // ||x_proj||^2
__device__ float g_colsum[DD];
__device__ float g_c0[DD];
__device__ float g_cp[DD];                           // unnormalized centroid
__device__ float g_c[DD];                            // centroid
__device__ float g_v[DD];                            // v = W^T c (fp32)
__device__ float g_cc;                               // ||c0||^2
__device__ float g_Z;
__device__ float g_bc;                               // b . c
__device__ float g_cnorm;
__device__ int   g_d2min_bits;

// ---------------- helpers ----------------
__device__ __forceinline__ uint32_t smem_u32(const void* p) {
    return (uint32_t)__cvta_generic_to_shared(p);
}
__device__ __forceinline__ void ldmx4(uint32_t* r, uint32_t addr) {
    asm volatile("ldmatrix.sync.aligned.m8n8.x4.shared.b16 {%0,%1,%2,%3}, [%4];"
                 : "=r"(r[0]), "=r"(r[1]), "=r"(r[2]), "=r"(r[3]) : "r"(addr));
}
__device__ __forceinline__ void mma16816(float* c, const uint32_t* a, const uint32_t* b) {
    asm volatile("mma.sync.aligned.m16n8k16.row.col.f32.bf16.bf16.f32 "
                 "{%0,%1,%2,%3}, {%4,%5,%6,%7}, {%8,%9}, {%0,%1,%2,%3};"
                 : "+f"(c[0]), "+f"(c[1]), "+f"(c[2]), "+f"(c[3])
                 : "r"(a[0]), "r"(a[1]), "r"(a[2]), "r"(a[3]), "r"(b[0]), "r"(b[1]));
}
__device__ __forceinline__ void cp_async16(uint32_t sdst, const void* gsrc) {
    asm volatile("cp.async.cg.shared.global [%0], [%1], 16;"
                 :: "r"(sdst), "l"(gsrc) : "memory");
}
__device__ __forceinline__ void cp_commit() {
    asm volatile("cp.async.commit_group;" ::: "memory");
}
__device__ __forceinline__ void cp_wait1() {
    asm volatile("cp.async.wait_group 1;" ::: "memory");
}

// ================= k0a: zero accumulators =================
__global__ void k0a_zero() {
    int i = blockIdx.x * blockDim.x + threadIdx.x;
    if (i < DD) { g_colsum[i] = 0.f; g_cp[i] = 0.f; g_v[i] = 0.f; }
    if (i == DD) g_Z = 0.f;
    if (i == DD + 1) g_d2min_bits = 0x7f7fffff;
}

// ================= k0b: W -> bf16 =================
__global__ void k0b_wcvt(const float* __restrict__ W) {
    int i = blockIdx.x * blockDim.x + threadIdx.x;
    int stride = gridDim.x * blockDim.x;
    for (int j = i; j < DD * DD; j += stride) g_wbf[j] = __float2bfloat16(W[j]);
}

// ================= k8: GEMM + fused pass1 (MLP-preserving version) ========
// R10 datapath (303.8us measured: warp tile m64 x j64, m128 CTA tile).
// A-phase: A1 pure streaming (no cross-lane deps) writes smem A, g_zbf, and
// per-thread ssq partials to smem scratch; A2 (post-sync) reduces row ssq
// (fp32-exact) and colsums (from bf16 tile). Eliminates the k1 pass.
#define K8_A    0
#define K8_B    131072
#define K8_BB   32768
#define K8_BV   196608
#define K8_NSQ  198656
#define K8_SCOL 199680
#define K8_SSP  201728                       // 64 x 65 floats = 16640 B
#define K8_SMEM 218368

__global__ void __launch_bounds__(256, 1)
k8_gemm(const float* __restrict__ z, const float* __restrict__ b_in, int N) {
    extern __shared__ char smem[];
    const uint32_t sbase = smem_u32(smem);
    const int tid = threadIdx.x, warp = tid >> 5, lane = tid & 31;
    const int m0 = blockIdx.x * 128;

    float* sbv  = (float*)(smem + K8_BV);
    float* snq  = (float*)(smem + K8_NSQ);
    float* scol = (float*)(smem + K8_SCOL);
    float* ssp  = (float*)(smem + K8_SSP);
    for (int i = tid; i < DD; i += 256) { sbv[i] = b_in[i]; scol[i] = 0.f; }
    if (tid < 128) snq[tid] = 0.f;
    __syncthreads();

    // ---- prefetch B buffers 0 and 1 (j256 x k64, pitch 128B) ----
#pragma unroll 1
    for (int h = 0; h < 2; h++) {
        const uint32_t bbuf = sbase + K8_B + (h & 1) * K8_BB;
        const int jc = h >> 3, kq = h & 7;
#pragma unroll
        for (int it = 0; it < 8; it++) {
            int idx = it * 256 + tid;
            int j = idx >> 3, ci = idx & 7;
            cp_async16(bbuf + j * 128 + ((ci ^ (j & 7)) << 4),
                       g_wbf + (size_t)(jc * 256 + j) * DD + kq * 64 + ci * 8);
        }
        cp_commit();
    }

    // ---- A1/A2: two half-tiles of 64 rows ----
#pragma unroll 1
    for (int hh = 0; hh < 2; hh++) {
        // A1: pure streaming (loads stay pipelined; no shuffles/atomics)
#pragma unroll 4
        for (int it = 0; it < 16; it++) {
            int idx = (hh * 16 + it) * 256 + tid;
            int r = idx >> 6, ci = idx & 63;      // r in [hh*64, hh*64+63]
            int grow = m0 + r;
            const bool valid = grow < N;
            int gsrc = valid ? grow : (N - 1);
            const float4* zp = (const float4*)(z + (size_t)gsrc * DD + ci * 8);
            float4 v0 = zp[0];
            float4 v1 = zp[1];
            __nv_bfloat162 p0 = __floats2bfloat162_rn(v0.x, v0.y);
            __nv_bfloat162 p1 = __floats2bfloat162_rn(v0.z, v0.w);
            __nv_bfloat162 p2 = __floats2bfloat162_rn(v1.x, v1.y);
            __nv_bfloat162 p3 = __floats2bfloat162_rn(v1.z, v1.w);
            uint4 val;
            val.x = *reinterpret_cast<uint32_t*>(&p0);
            val.y = *reinterpret_cast<uint32_t*>(&p1);
            val.z = *reinterpret_cast<uint32_t*>(&p2);
            val.w = *reinterpret_cast<uint32_t*>(&p3);
            *(uint4*)(smem + K8_A + r * 1024 + ((ci ^ (r & 7)) << 4)) = val;
            float p = 0.f;
            if (valid) {
                __stcs((uint4*)(g_zbf + (size_t)grow * DD + ci * 8), val);
                p = v0.x * v0.x + v0.y * v0.y + v0.z * v0.z + v0.w * v0.w
                  + v1.x * v1.x + v1.y * v1.y + v1.z * v1.z + v1.w * v1.w;
            }
            ssp[(r & 63) * 65 + ci] = p;          // padded: conflict-free
        }
        __syncthreads();
        // A2a: reduce row ssq (fp32-exact); 4 threads per row
        {
            int row64 = tid >> 2, part = tid & 3;
            const float* sp = ssp + row64 * 65 + part * 16;
            float s4 = 0.f;
#pragma unroll
            for (int j = 0; j < 16; j++) s4 += sp[j];
            s4 += __shfl_xor_sync(0xffffffffu, s4, 1);
            s4 += __shfl_xor_sync(0xffffffffu, s4, 2);
            int grow = m0 + hh * 64 + row64;
            if (part == 0 && grow < N) g_s[grow] = s4;
        }
        __syncthreads();                          // ssp reused next half
    }

    // ---- A2b: colsums from the bf16 A tile in smem ----
    {
        int ci = tid & 63, q = tid >> 6;
        int nval = N - m0; if (nval > 128) nval = 128;
        float cs[8];
#pragma unroll
        for (int e = 0; e < 8; e++) cs[e] = 0.f;
        for (int rr = 0; rr < 32; rr++) {
            int r = q * 32 + rr;
            if (r >= nval) break;
            uint4 u = *(const uint4*)(smem + K8_A + r * 1024 + ((ci ^ (r & 7)) << 4));
            const __nv_bfloat162* pp = (const __nv_bfloat162*)&u;
            float2 f0 = __bfloat1622float2(pp[0]);
            float2 f1 = __bfloat1622float2(pp[1]);
            float2 f2 = __bfloat1622float2(pp[2]);
            float2 f3 = __bfloat1622float2(pp[3]);
            cs[0] += f0.x; cs[1] += f0.y; cs[2] += f1.x; cs[3] += f1.y;
            cs[4] += f2.x; cs[5] += f2.y; cs[6] += f3.x; cs[7] += f3.y;
        }
#pragma unroll
        for (int e = 0; e < 8; e++) atomicAdd(&scol[ci * 8 + e], cs[e]);
    }
    __syncthreads();
    for (int i = tid; i < DD; i += 256) atomicAdd(&g_colsum[i], scol[i]);

    // ---- warp coords: mg = warp&1 (m64), jg = warp>>1 (j64 of j256) ----
    const int mg = warp & 1, jg = warp >> 1;
    const int mbase = mg * 64;
    const uint32_t swa = lane & 7;
    const uint32_t a0base = sbase + K8_A + (uint32_t)(mbase + (lane & 15)) * 1024;
    const int jrow = (lane & 7) + ((lane >> 4) << 3);
    const uint32_t brow_off = (uint32_t)(jg * 64 + jrow) * 128;
    const uint32_t ciBofs = (lane >> 3) & 1;
    const uint32_t ciAofs = lane >> 4;

    float acc[32][4];
#pragma unroll
    for (int t = 0; t < 32; t++)
#pragma unroll
        for (int e = 0; e < 4; e++) acc[t][e] = 0.f;
    float nsq[4][2] = {{0.f,0.f},{0.f,0.f},{0.f,0.f},{0.f,0.f}};

    for (int h = 0; h < 16; h++) {           // jc = h>>3 (j256), kq = h&7 (k64)
        const int buf = h & 1, jc = h >> 3, kq = h & 7;
        cp_wait1();
        __syncthreads();
        const uint32_t b0base = sbase + K8_B + buf * K8_BB + brow_off;

#pragma unroll
        for (int ktl = 0; ktl < 4; ktl++) {  // k16 steps within k64
            uint32_t a[4][4], bb[4][4];
            uint32_t ciA = (uint32_t)(kq * 4 + ktl) * 2 + ciAofs;
            uint32_t adr = a0base + ((ciA ^ swa) << 4);
            ldmx4(a[0], adr);
            ldmx4(a[1], adr + 16 * 1024);
            ldmx4(a[2], adr + 32 * 1024);
            ldmx4(a[3], adr + 48 * 1024);
            uint32_t ciB = (uint32_t)ktl * 2 + ciBofs;
            uint32_t bdr = b0base + ((ciB ^ swa) << 4);
            ldmx4(bb[0], bdr);
            ldmx4(bb[1], bdr + 16 * 128);
            ldmx4(bb[2], bdr + 32 * 128);
            ldmx4(bb[3], bdr + 48 * 128);
#pragma unroll
            for (int mt = 0; mt < 4; mt++) {
#pragma unroll
                for (int nt = 0; nt < 8; nt++)
                    mma16816(acc[mt * 8 + nt], a[mt], bb[nt >> 1] + (nt & 1) * 2);
            }
        }
        __syncthreads();   // all warps done with buf before refill

        if (kq == 7) {
            // j256 chunk complete over k512: fold (acc + b)^2, reset acc
#pragma unroll
            for (int mt = 0; mt < 4; mt++)
#pragma unroll
                for (int nt = 0; nt < 8; nt++) {
                    int jglob = jc * 256 + jg * 64 + nt * 8 + (lane & 3) * 2;
                    float bx = sbv[jglob], by = sbv[jglob + 1];
                    float* a = acc[mt * 8 + nt];
                    float v0 = a[0] + bx, v1 = a[1] + by;
                    float v2 = a[2] + bx, v3 = a[3] + by;
                    nsq[mt][0] += v0 * v0 + v1 * v1;
                    nsq[mt][1] += v2 * v2 + v3 * v3;
                    a[0] = 0.f; a[1] = 0.f; a[2] = 0.f; a[3] = 0.f;
                }
        }
        if (h + 2 < 16) {
            const int h2 = h + 2;
            const uint32_t bbuf = sbase + K8_B + buf * K8_BB;
            const int jc2 = h2 >> 3, kq2 = h2 & 7;
#pragma unroll
            for (int it = 0; it < 8; it++) {
                int idx = it * 256 + tid;
                int j = idx >> 3, ci = idx & 7;
                cp_async16(bbuf + j * 128 + ((ci ^ (j & 7)) << 4),
                           g_wbf + (size_t)(jc2 * 256 + j) * DD + kq2 * 64 + ci * 8);
            }
        }
        cp_commit();
    }

    // ---- merge lane partials: quad lanes share a row ----
#pragma unroll
    for (int mt = 0; mt < 4; mt++)
#pragma unroll
        for (int hh = 0; hh < 2; hh++) {
            float vn = nsq[mt][hh];
            vn += __shfl_xor_sync(0xffffffffu, vn, 1);
            vn += __shfl_xor_sync(0xffffffffu, vn, 2);
            if ((lane & 3) == 0)
                atomicAdd(&snq[mbase + mt * 16 + hh * 8 + (lane >> 2)], vn);
        }
    __syncthreads();

    if (tid < 128 && m0 + tid < N) g_nsq[m0 + tid] = snq[tid];
}

// ================= k2: c0 = colsum/N, cc = ||c0||^2 =================
__global__ void k2_c0(int N) {
    __shared__ float red[16];
    const int tid = threadIdx.x; // 512
    float c0 = g_colsum[tid] / (float)N;
    g_c0[tid] = c0;
    float sq = c0 * c0;
#pragma unroll
    for (int o = 16; o > 0; o >>= 1) sq += __shfl_xor_sync(0xffffffffu, sq, o);
    if ((tid & 31) == 0) red[tid >> 5] = sq;
    __syncthreads();
    if (tid < 16) {
        float s = red[tid];
#pragma unroll
        for (int o = 8; o > 0; o >>= 1) s += __shfl_xor_sync(0xffffu, s, o);
        if (tid == 0) g_cc = s;
    }
}

// ================= k3: d2 = s - 2 h.c0 + cc (bf16 h), block-min ==========
__global__ void k3_d2(int N) {
    __shared__ __align__(16) float c0s[DD];
    __shared__ int smin;
    const int tid = threadIdx.x, wid = tid >> 5, lane = tid & 31;
    for (int i = tid; i < DD; i += blockDim.x) c0s[i] = g_c0[i];
    if (tid == 0) smin = 0x7f7fffff;
    __syncthreads();
    const float cc = g_cc;
    const int gw = blockIdx.x * (blockDim.x >> 5) + wid;
    const int nw = gridDim.x * (blockDim.x >> 5);
    for (int r4 = gw * 4; r4 < N; r4 += nw * 4) {
        float t[4] = {0.f, 0.f, 0.f, 0.f};
        int nr = (N - r4 < 4) ? (N - r4) : 4;
#pragma unroll
        for (int q = 0; q < 4; q++) {
            int row = r4 + ((q < nr) ? q : 0);
#pragma unroll
            for (int c = 0; c < 2; c++) {
                uint4 u = __ldcs((const uint4*)(g_zbf + (size_t)row * DD + c * 256 + lane * 8));
                const __nv_bfloat162* p = (const __nv_bfloat162*)&u;
                float4 cv0 = ((const float4*)c0s)[c * 64 + lane * 2];
                float4 cv1 = ((const float4*)c0s)[c * 64 + lane * 2 + 1];
                float2 f0 = __bfloat1622float2(p[0]);
                float2 f1 = __bfloat1622float2(p[1]);
                float2 f2 = __bfloat1622float2(p[2]);
                float2 f3 = __bfloat1622float2(p[3]);
                t[q] += f0.x * cv0.x + f0.y * cv0.y + f1.x * cv0.z + f1.y * cv0.w
                      + f2.x * cv1.x + f2.y * cv1.y + f3.x * cv1.z + f3.y * cv1.w;
            }
        }
#pragma unroll
        for (int q = 0; q < 4; q++)
#pragma unroll
            for (int o = 16; o > 0; o >>= 1)
                t[q] += __shfl_xor_sync(0xffffffffu, t[q], o);
        if (lane == 0) {
            int lmin = 0x7f7fffff;
#pragma unroll
            for (int q = 0; q < 4; q++) {
                if (q < nr) {
                    float d2 = g_s[r4 + q] - 2.f * t[q] + cc;
                    g_d2[r4 + q] = d2;
                    int bits = __float_as_int(d2);
                    if (bits < lmin) lmin = bits;
                }
            }
            atomicMin(&smin, lmin);
        }
    }
    __syncthreads();
    if (tid == 0) atomicMin(&g_d2min_bits, smin);
}

// ================= k45: Z + unnormalized centroid c' =====================
__global__ void k45_Zc(const float* __restrict__ z, int N) {
    __shared__ float red[8];
    const int tid = threadIdx.x, lane = tid & 31;
    const float d2min = __int_as_float(g_d2min_bits);
    const int gidx = blockIdx.x * blockDim.x + tid;
    const int stride = gridDim.x * blockDim.x;
    const int numIter = (N + stride - 1) / stride;
    float zpart = 0.f;
    for (int i = 0; i < numIter; i++) {
        int r = gidx + i * stride;
        float e = 0.f;
        if (r < N) e = __expf((d2min - g_d2[r]) * TAU_INV);
        zpart += e;
        unsigned mask = __ballot_sync(0xffffffffu, e > 1e-13f);
        while (mask) {
            int src = __ffs(mask) - 1;
            mask &= mask - 1;
            int rb = __shfl_sync(0xffffffffu, r, src);
            float eb = __shfl_sync(0xffffffffu, e, src);
            const float* zr = z + (size_t)rb * DD;
#pragma unroll
            for (int c = 0; c < 16; c++)
                atomicAdd(&g_cp[c * 32 + lane], eb * zr[c * 32 + lane]);
        }
    }
#pragma unroll
    for (int o = 16; o > 0; o >>= 1) zpart += __shfl_xor_sync(0xffffffffu, zpart, o);
    if (lane == 0) red[tid >> 5] = zpart;
    __syncthreads();
    if (tid < 8) {
        float t = red[tid];
#pragma unroll
        for (int o = 4; o > 0; o >>= 1) t += __shfl_xor_sync(0xffu, t, o);
        if (tid == 0) atomicAdd(&g_Z, t);
    }
}

// ================= k7: c = c'/Z, cnorm, bc =================
__global__ void k7_norm(const float* __restrict__ b) {
    __shared__ float redc[16], redb[16];
    const int tid = threadIdx.x; // 512
    const float invZ = 1.f / g_Z;
    float cv = g_cp[tid] * invZ;
    g_c[tid] = cv;
    float pc = cv * cv;
    float pb = cv * b[tid];
#pragma unroll
    for (int o = 16; o > 0; o >>= 1) {
        pc += __shfl_xor_sync(0xffffffffu, pc, o);
        pb += __shfl_xor_sync(0xffffffffu, pb, o);
    }
    if ((tid & 31) == 0) { redc[tid >> 5] = pc; redb[tid >> 5] = pb; }
    __syncthreads();
    if (tid < 16) {
        float sc = redc[tid], sb = redb[tid];
#pragma unroll
        for (int o = 8; o > 0; o >>= 1) {
            sc += __shfl_xor_sync(0xffffu, sc, o);
            sb += __shfl_xor_sync(0xffffu, sb, o);
        }
        if (tid == 0) { g_cnorm = fmaxf(sqrtf(sc), EPS); g_bc = sb; }
    }
}

// ================= k6: v = W^T c (fp32 exact) =================
__global__ void k6_v(const float* __restrict__ W) {
    __shared__ float cs[16];
    const int tid = threadIdx.x; // 512
    const int j0 = blockIdx.x * 16;
    if (tid < 16) cs[tid] = g_c[j0 + tid];
    __syncthreads();
    float acc = 0.f;
#pragma unroll
    for (int jj = 0; jj < 16; jj++)
        acc += cs[jj] * W[(size_t)(j0 + jj) * DD + tid];
    atomicAdd(&g_v[tid], acc);
}

// ================= k9: dot + final dist (fused epilogue) =================
__global__ void k9_dot(float* __restrict__ out, int N) {
    __shared__ __align__(16) float sv[DD];
    const int tid = threadIdx.x, wid = tid >> 5, lane = tid & 31;
    for (int i = tid; i < DD; i += blockDim.x) sv[i] = g_v[i];
    __syncthreads();
    const float bc = g_bc, cnorm = g_cnorm;
    const int gw = blockIdx.x * (blockDim.x >> 5) + wid;
    const int nw = gridDim.x * (blockDim.x >> 5);
    for (int row = gw; row < N; row += nw) {
        float d = 0.f;
#pragma unroll
        for (int c = 0; c < 2; c++) {
            uint4 u = __ldcs((const uint4*)(g_zbf + (size_t)row * DD + c * 256 + lane * 8));
            const __nv_bfloat162* p = (const __nv_bfloat162*)&u;
            float4 v0 = ((const float4*)sv)[c * 64 + lane * 2];
            float4 v1 = ((const float4*)sv)[c * 64 + lane * 2 + 1];
            float2 f0 = __bfloat1622float2(p[0]);
            float2 f1 = __bfloat1622float2(p[1]);
            float2 f2 = __bfloat1622float2(p[2]);
            float2 f3 = __bfloat1622float2(p[3]);
            d += f0.x * v0.x + f0.y * v0.y + f1.x * v0.z + f1.y * v0.w
               + f2.x * v1.x + f2.y * v1.y + f3.x * v1.z + f3.y * v1.w;
        }
#pragma unroll
        for (int o = 16; o > 0; o >>= 1) d += __shfl_xor_sync(0xffffffffu, d, o);
        if (lane == 0) {
            float nx = fmaxf(sqrtf(g_nsq[row]), EPS);
            out[row] = 1.0f - (d + bc) / (nx * cnorm);
        }
    }
}

// ================= launch (single stream; k1 fused into GEMM) =============
extern "C" void kernel_launch(void* const* d_in, const int* in_sizes, int n_in,
                              void* d_out, int out_size) {
    const float* z = (const float*)d_in[0];
    const float* W = (const float*)d_in[1];
    const float* b = (const float*)d_in[2];
    float* out = (float*)d_out;
    const int N = in_sizes[0] / DD;

    k0a_zero<<<3, 256>>>();
    k0b_wcvt<<<512, 256>>>(W);
    cudaFuncSetAttribute(k8_gemm, cudaFuncAttributeMaxDynamicSharedMemorySize, K8_SMEM);
    k8_gemm<<<(N + 127) / 128, 256, K8_SMEM>>>(z, b, N);
    k2_c0<<<1, 512>>>(N);
    k3_d2<<<1184, 256>>>(N);
    k45_Zc<<<592, 256>>>(z, N);
    k7_norm<<<1, 512>>>(b);
    k6_v<<<32, 512>>>(W);
    k9_dot<<<1184, 256>>>(out, N);
}

// round 17
// speedup vs baseline: 1.0789x; 1.0789x over previous
#include <cuda_runtime.h>
#include <cuda_bf16.h>
#include <cstdint>

#define DD 512
#define MAXN 200000
#define TAU_INV 2.0f
#define EPS 1e-8f

// ---------------- device scratch (no allocations allowed) ----------------
__device__ __align__(256) __nv_bfloat16 g_zbf[(size_t)MAXN * DD];   // z in bf16
__device__ __align__(256) __nv_bfloat16 g_wbf[DD * DD];             // W in bf16
__device__ float g_s[MAXN];                          // row sumsq of z (fp32)
__device__ float g_d2[MAXN];
__device__ float g_colsum[DD];
__device__ float g_c0[DD];                           // init centroid
__device__ float g_cp[DD];                           // unnormalized softmax centroid
__device__ float g_c[DD];                            // normalized centroid
__device__ float g_cc;                               // ||c0||^2
__device__ float g_Z;                                // softmax partition
__device__ float g_cnorm;                            // max(||c||, eps)
__device__ int   g_d2min_bits;

// ---------------- helpers ----------------
__device__ __forceinline__ uint32_t smem_u32(const void* p) {
    return (uint32_t)__cvta_generic_to_shared(p);
}
__device__ __forceinline__ void ldmx4(uint32_t* r, uint32_t addr) {
    asm volatile("ldmatrix.sync.aligned.m8n8.x4.shared.b16 {%0,%1,%2,%3}, [%4];"
                 : "=r"(r[0]), "=r"(r[1]), "=r"(r[2]), "=r"(r[3]) : "r"(addr));
}
__device__ __forceinline__ void mma16816(float* c, const uint32_t* a, const uint32_t* b) {
    asm volatile("mma.sync.aligned.m16n8k16.row.col.f32.bf16.bf16.f32 "
                 "{%0,%1,%2,%3}, {%4,%5,%6,%7}, {%8,%9}, {%0,%1,%2,%3};"
                 : "+f"(c[0]), "+f"(c[1]), "+f"(c[2]), "+f"(c[3])
                 : "r"(a[0]), "r"(a[1]), "r"(a[2]), "r"(a[3]), "r"(b[0]), "r"(b[1]));
}
__device__ __forceinline__ void cp_async16(uint32_t sdst, const void* gsrc) {
    asm volatile("cp.async.cg.shared.global [%0], [%1], 16;"
                 :: "r"(sdst), "l"(gsrc) : "memory");
}
__device__ __forceinline__ void cp_commit() {
    asm volatile("cp.async.commit_group;" ::: "memory");
}
__device__ __forceinline__ void cp_wait1() {
    asm volatile("cp.async.wait_group 1;" ::: "memory");
}

// ================= k0: init scratch + W -> bf16 =================
__global__ void k0_init(const float* __restrict__ W) {
    int i = blockIdx.x * blockDim.x + threadIdx.x;
    int stride = gridDim.x * blockDim.x;
    for (int j = i; j < DD * DD; j += stride) g_wbf[j] = __float2bfloat16(W[j]);
    if (i < DD) { g_colsum[i] = 0.f; g_cp[i] = 0.f; }
    if (i == 0) { g_Z = 0.f; g_d2min_bits = 0x7f7fffff; }
}

// ================= k1: colsums + row sumsq + z->bf16 (2 rows/iter) ========
__global__ void k1_pass1(const float* __restrict__ z, int N) {
    __shared__ float scol[DD];
    const int tid = threadIdx.x, wid = tid >> 5, lane = tid & 31;
    for (int i = tid; i < DD; i += blockDim.x) scol[i] = 0.f;
    __syncthreads();
    const int gw = blockIdx.x * (blockDim.x >> 5) + wid;
    const int nw = gridDim.x * (blockDim.x >> 5);
    float cs[16];
#pragma unroll
    for (int i = 0; i < 16; i++) cs[i] = 0.f;
    for (int r2 = gw * 2; r2 < N; r2 += nw * 2) {
        const int nr = (N - r2 < 2) ? (N - r2) : 2;
        const float4* zr0 = (const float4*)(z + (size_t)r2 * DD);
        const float4* zr1 = (const float4*)(z + (size_t)(r2 + ((nr > 1) ? 1 : 0)) * DD);
        float4 va[4], vb[4];
#pragma unroll
        for (int c = 0; c < 4; c++) {          // 8 outstanding loads
            va[c] = __ldcs(zr0 + c * 32 + lane);
            vb[c] = __ldcs(zr1 + c * 32 + lane);
        }
        float ssq0 = 0.f, ssq1 = 0.f;
#pragma unroll
        for (int c = 0; c < 4; c++) {
            float4 v = va[c];
            ssq0 += v.x * v.x + v.y * v.y + v.z * v.z + v.w * v.w;
            cs[c * 4 + 0] += v.x; cs[c * 4 + 1] += v.y;
            cs[c * 4 + 2] += v.z; cs[c * 4 + 3] += v.w;
            __nv_bfloat162 b0 = __floats2bfloat162_rn(v.x, v.y);
            __nv_bfloat162 b1 = __floats2bfloat162_rn(v.z, v.w);
            float2 u;
            u.x = __uint_as_float(*reinterpret_cast<uint32_t*>(&b0));
            u.y = __uint_as_float(*reinterpret_cast<uint32_t*>(&b1));
            __stcs((float2*)(g_zbf + (size_t)r2 * DD + c * 128 + lane * 4), u);
        }
        if (nr > 1) {
#pragma unroll
            for (int c = 0; c < 4; c++) {
                float4 v = vb[c];
                ssq1 += v.x * v.x + v.y * v.y + v.z * v.z + v.w * v.w;
                cs[c * 4 + 0] += v.x; cs[c * 4 + 1] += v.y;
                cs[c * 4 + 2] += v.z; cs[c * 4 + 3] += v.w;
                __nv_bfloat162 b0 = __floats2bfloat162_rn(v.x, v.y);
                __nv_bfloat162 b1 = __floats2bfloat162_rn(v.z, v.w);
                float2 u;
                u.x = __uint_as_float(*reinterpret_cast<uint32_t*>(&b0));
                u.y = __uint_as_float(*reinterpret_cast<uint32_t*>(&b1));
                __stcs((float2*)(g_zbf + (size_t)(r2 + 1) * DD + c * 128 + lane * 4), u);
            }
        }
#pragma unroll
        for (int o = 16; o > 0; o >>= 1) {
            ssq0 += __shfl_xor_sync(0xffffffffu, ssq0, o);
            ssq1 += __shfl_xor_sync(0xffffffffu, ssq1, o);
        }
        if (lane == 0) {
            g_s[r2] = ssq0;
            if (nr > 1) g_s[r2 + 1] = ssq1;
        }
    }
#pragma unroll
    for (int c = 0; c < 4; c++)
#pragma unroll
        for (int e = 0; e < 4; e++)
            atomicAdd(&scol[c * 128 + lane * 4 + e], cs[c * 4 + e]);
    __syncthreads();
    for (int i = tid; i < DD; i += blockDim.x) atomicAdd(&g_colsum[i], scol[i]);
}

// ================= k2: c0 = colsum/N, cc = ||c0||^2 =================
__global__ void k2_c0(int N) {
    __shared__ float red[16];
    const int tid = threadIdx.x; // 512
    float c0 = g_colsum[tid] / (float)N;
    g_c0[tid] = c0;
    float sq = c0 * c0;
#pragma unroll
    for (int o = 16; o > 0; o >>= 1) sq += __shfl_xor_sync(0xffffffffu, sq, o);
    if ((tid & 31) == 0) red[tid >> 5] = sq;
    __syncthreads();
    if (tid < 16) {
        float s = red[tid];
#pragma unroll
        for (int o = 8; o > 0; o >>= 1) s += __shfl_xor_sync(0xffffu, s, o);
        if (tid == 0) g_cc = s;
    }
}

// ================= k3: d2 = s - 2 h.c0 + cc (bf16 h), block-min ==========
__global__ void k3_d2(int N) {
    __shared__ __align__(16) float c0s[DD];
    __shared__ int smin;
    const int tid = threadIdx.x, wid = tid >> 5, lane = tid & 31;
    for (int i = tid; i < DD; i += blockDim.x) c0s[i] = g_c0[i];
    if (tid == 0) smin = 0x7f7fffff;
    __syncthreads();
    const float cc = g_cc;
    const int gw = blockIdx.x * (blockDim.x >> 5) + wid;
    const int nw = gridDim.x * (blockDim.x >> 5);
    for (int r4 = gw * 4; r4 < N; r4 += nw * 4) {
        float t[4] = {0.f, 0.f, 0.f, 0.f};
        int nr = (N - r4 < 4) ? (N - r4) : 4;
#pragma unroll
        for (int q = 0; q < 4; q++) {
            int row = r4 + ((q < nr) ? q : 0);
#pragma unroll
            for (int c = 0; c < 2; c++) {
                uint4 u = __ldcs((const uint4*)(g_zbf + (size_t)row * DD + c * 256 + lane * 8));
                const __nv_bfloat162* p = (const __nv_bfloat162*)&u;
                float4 cv0 = ((const float4*)c0s)[c * 64 + lane * 2];
                float4 cv1 = ((const float4*)c0s)[c * 64 + lane * 2 + 1];
                float2 f0 = __bfloat1622float2(p[0]);
                float2 f1 = __bfloat1622float2(p[1]);
                float2 f2 = __bfloat1622float2(p[2]);
                float2 f3 = __bfloat1622float2(p[3]);
                t[q] += f0.x * cv0.x + f0.y * cv0.y + f1.x * cv0.z + f1.y * cv0.w
                      + f2.x * cv1.x + f2.y * cv1.y + f3.x * cv1.z + f3.y * cv1.w;
            }
        }
#pragma unroll
        for (int q = 0; q < 4; q++)
#pragma unroll
            for (int o = 16; o > 0; o >>= 1)
                t[q] += __shfl_xor_sync(0xffffffffu, t[q], o);
        if (lane == 0) {
            int lmin = 0x7f7fffff;
#pragma unroll
            for (int q = 0; q < 4; q++) {
                if (q < nr) {
                    float d2 = g_s[r4 + q] - 2.f * t[q] + cc;
                    g_d2[r4 + q] = d2;
                    int bits = __float_as_int(d2);
                    if (bits < lmin) lmin = bits;
                }
            }
            atomicMin(&smin, lmin);
        }
    }
    __syncthreads();
    if (tid == 0) atomicMin(&g_d2min_bits, smin);
}

// ================= k45: Z + unnormalized centroid c' (uniform trips) ======
__global__ void k45_Zc(const float* __restrict__ z, int N) {
    __shared__ float red[8];
    const int tid = threadIdx.x, lane = tid & 31;
    const float d2min = __int_as_float(g_d2min_bits);
    const int gidx = blockIdx.x * blockDim.x + tid;
    const int stride = gridDim.x * blockDim.x;
    const int numIter = (N + stride - 1) / stride;   // identical for all threads
    float zpart = 0.f;
    for (int i = 0; i < numIter; i++) {
        int r = gidx + i * stride;
        float e = 0.f;
        if (r < N) e = __expf((d2min - g_d2[r]) * TAU_INV);
        zpart += e;
        unsigned mask = __ballot_sync(0xffffffffu, e > 1e-13f);
        while (mask) {
            int src = __ffs(mask) - 1;
            mask &= mask - 1;
            int rb = __shfl_sync(0xffffffffu, r, src);
            float eb = __shfl_sync(0xffffffffu, e, src);
            const float* zr = z + (size_t)rb * DD;
#pragma unroll
            for (int c = 0; c < 16; c++)
                atomicAdd(&g_cp[c * 32 + lane], eb * zr[c * 32 + lane]);
        }
    }
#pragma unroll
    for (int o = 16; o > 0; o >>= 1) zpart += __shfl_xor_sync(0xffffffffu, zpart, o);
    if (lane == 0) red[tid >> 5] = zpart;
    __syncthreads();
    if (tid < 8) {
        float t = red[tid];
#pragma unroll
        for (int o = 4; o > 0; o >>= 1) t += __shfl_xor_sync(0xffu, t, o);
        if (tid == 0) atomicAdd(&g_Z, t);
    }
}

// ================= k7: c = c'/Z, cnorm =================
__global__ void k7_norm() {
    __shared__ float red[16];
    const int tid = threadIdx.x; // 512
    const float invZ = 1.f / g_Z;
    float cv = g_cp[tid] * invZ;
    g_c[tid] = cv;
    float pc = cv * cv;
#pragma unroll
    for (int o = 16; o > 0; o >>= 1) pc += __shfl_xor_sync(0xffffffffu, pc, o);
    if ((tid & 31) == 0) red[tid >> 5] = pc;
    __syncthreads();
    if (tid < 16) {
        float sc = red[tid];
#pragma unroll
        for (int o = 8; o > 0; o >>= 1) sc += __shfl_xor_sync(0xffffu, sc, o);
        if (tid == 0) g_cnorm = fmaxf(sqrtf(sc), EPS);
    }
}

// ================= k8: mma.sync GEMM, cp.async-pipelined B, fused epilogue ====
// (R4 verified at 482.7us): A 128x512 bf16 resident; B 2 half-buffers
// (64 j x 256 k) double-buffered; warp tile m32 x j32; epilogue folds both
// (acc+b)^2 (norm) and (acc+b)*c (cosine numerator). No k6/k9 needed.
#define K8_A    0
#define K8_B    131072
#define K8_BHB  32768
#define K8_C    196608
#define K8_BV   198656
#define K8_NSQ  200704
#define K8_COS  201216
#define K8_SMEM 201728

__global__ void __launch_bounds__(256, 1)
k8_gemm(const float* __restrict__ b_in, float* __restrict__ out, int N) {
    extern __shared__ char smem[];
    const uint32_t sbase = smem_u32(smem);
    const int tid = threadIdx.x, warp = tid >> 5, lane = tid & 31;
    const int m0 = blockIdx.x * 128;

    float* sc  = (float*)(smem + K8_C);
    float* sbv = (float*)(smem + K8_BV);
    float* snq = (float*)(smem + K8_NSQ);
    float* sco = (float*)(smem + K8_COS);

    for (int i = tid; i < DD; i += 256) { sc[i] = g_c[i]; sbv[i] = b_in[i]; }
    if (tid < 128) { snq[tid] = 0.f; sco[tid] = 0.f; }

    // ---- prefetch B halves 0 and 1 via cp.async ----
#pragma unroll 1
    for (int h = 0; h < 2; h++) {
        const uint32_t bbuf = sbase + K8_B + (h & 1) * K8_BHB;
        const int jc = h >> 1, kh = h & 1;
#pragma unroll
        for (int it = 0; it < 8; it++) {
            int idx = it * 256 + tid;
            int j = idx >> 5, ci = idx & 31;
            cp_async16(bbuf + j * 512 + ((ci ^ (j & 7)) << 4),
                       g_wbf + (size_t)(jc * 64 + j) * DD + kh * 256 + ci * 8);
        }
        cp_commit();
    }

    // ---- load A: 128 rows x 512 bf16 ----
#pragma unroll
    for (int it = 0; it < 32; it++) {
        int idx = it * 256 + tid;
        int r = idx >> 6, ci = idx & 63;
        int grow = m0 + r; if (grow > N - 1) grow = N - 1;
        uint4 val = *(const uint4*)(g_zbf + (size_t)grow * DD + ci * 8);
        *(uint4*)(smem + K8_A + r * 1024 + ((ci ^ (r & 7)) << 4)) = val;
    }

    // ---- warp tiling: mg = warp&3 (m32), jg = warp>>2 (j32 of 64-chunk) --
    const int mg = warp & 3, jg = warp >> 2;
    const int mbase = mg * 32;
    const uint32_t swa = lane & 7;
    const uint32_t a0base = sbase + K8_A + (uint32_t)(mbase + (lane & 15)) * 1024;
    const int jrow = (lane & 7) + ((lane >> 4) << 3);
    const uint32_t brow_off = (uint32_t)(jg * 32 + jrow) * 512;
    const uint32_t ciBofs = (lane >> 3) & 1;
    const uint32_t ciAofs = lane >> 4;

    float acc[8][4];
#pragma unroll
    for (int t = 0; t < 8; t++)
#pragma unroll
        for (int e = 0; e < 4; e++) acc[t][e] = 0.f;
    float nsq[2][2] = {{0.f, 0.f}, {0.f, 0.f}};
    float cqs[2][2] = {{0.f, 0.f}, {0.f, 0.f}};

    for (int h = 0; h < 16; h++) {
        const int buf = h & 1, kh = h & 1, jc = h >> 1;
        cp_wait1();
        __syncthreads();
        const uint32_t b0base = sbase + K8_B + buf * K8_BHB + brow_off;

#pragma unroll 4
        for (int ktl = 0; ktl < 16; ktl++) {
            uint32_t a0[4], a1[4], b0[4], b1[4];
            uint32_t ciA = (uint32_t)(kh * 16 + ktl) * 2 + ciAofs;
            uint32_t adr = a0base + ((ciA ^ swa) << 4);
            ldmx4(a0, adr);
            ldmx4(a1, adr + 16 * 1024);
            uint32_t ciB = (uint32_t)ktl * 2 + ciBofs;
            uint32_t bdr = b0base + ((ciB ^ swa) << 4);
            ldmx4(b0, bdr);
            ldmx4(b1, bdr + 16 * 512);
            mma16816(acc[0], a0, b0 + 0);
            mma16816(acc[1], a0, b0 + 2);
            mma16816(acc[2], a0, b1 + 0);
            mma16816(acc[3], a0, b1 + 2);
            mma16816(acc[4], a1, b0 + 0);
            mma16816(acc[5], a1, b0 + 2);
            mma16816(acc[6], a1, b1 + 0);
            mma16816(acc[7], a1, b1 + 2);
        }
        __syncthreads();   // all warps done with buf before refill

        if (h & 1) {
            // jc complete: fold (acc + b)^2 and (acc + b)*c, reset acc
#pragma unroll
            for (int mt = 0; mt < 2; mt++)
#pragma unroll
                for (int nt = 0; nt < 4; nt++) {
                    int jglob = jc * 64 + jg * 32 + nt * 8 + (lane & 3) * 2;
                    float bx = sbv[jglob], by = sbv[jglob + 1];
                    float cx = sc[jglob],  cy = sc[jglob + 1];
                    float* a = acc[mt * 4 + nt];
                    float v0 = a[0] + bx, v1 = a[1] + by;
                    float v2 = a[2] + bx, v3 = a[3] + by;
                    nsq[mt][0] += v0 * v0 + v1 * v1;
                    nsq[mt][1] += v2 * v2 + v3 * v3;
                    cqs[mt][0] += v0 * cx + v1 * cy;
                    cqs[mt][1] += v2 * cx + v3 * cy;
                    a[0] = 0.f; a[1] = 0.f; a[2] = 0.f; a[3] = 0.f;
                }
        }
        if (h + 2 < 16) {
            const uint32_t bbuf = sbase + K8_B + buf * K8_BHB;
            const int jc2 = (h + 2) >> 1, kh2 = (h + 2) & 1;
#pragma unroll
            for (int it = 0; it < 8; it++) {
                int idx = it * 256 + tid;
                int j = idx >> 5, ci = idx & 31;
                cp_async16(bbuf + j * 512 + ((ci ^ (j & 7)) << 4),
                           g_wbf + (size_t)(jc2 * 64 + j) * DD + kh2 * 256 + ci * 8);
            }
        }
        cp_commit();
    }

    // ---- merge lane partials: quad lanes share a row ----
#pragma unroll
    for (int mt = 0; mt < 2; mt++)
#pragma unroll
        for (int hh = 0; hh < 2; hh++) {
            float vn = nsq[mt][hh], vc = cqs[mt][hh];
            vn += __shfl_xor_sync(0xffffffffu, vn, 1);
            vn += __shfl_xor_sync(0xffffffffu, vn, 2);
            vc += __shfl_xor_sync(0xffffffffu, vc, 1);
            vc += __shfl_xor_sync(0xffffffffu, vc, 2);
            if ((lane & 3) == 0) {
                int r = mbase + mt * 16 + hh * 8 + (lane >> 2);
                atomicAdd(&snq[r], vn);
                atomicAdd(&sco[r], vc);
            }
        }
    __syncthreads();

    if (tid < 128 && m0 + tid < N) {
        float nx = fmaxf(sqrtf(snq[tid]), EPS);
        out[m0 + tid] = 1.0f - sco[tid] / (nx * g_cnorm);
    }
}

// ================= launch =================
extern "C" void kernel_launch(void* const* d_in, const int* in_sizes, int n_in,
                              void* d_out, int out_size) {
    const float* z = (const float*)d_in[0];
    const float* W = (const float*)d_in[1];
    const float* b = (const float*)d_in[2];
    float* out = (float*)d_out;
    const int N = in_sizes[0] / DD;

    k0_init<<<1024, 256>>>(W);
    k1_pass1<<<1184, 256>>>(z, N);
    k2_c0<<<1, 512>>>(N);
    k3_d2<<<1184, 256>>>(N);
    k45_Zc<<<592, 256>>>(z, N);
    k7_norm<<<1, 512>>>();
    cudaFuncSetAttribute(k8_gemm, cudaFuncAttributeMaxDynamicSharedMemorySize, K8_SMEM);
    k8_gemm<<<(N + 127) / 128, 256, K8_SMEM>>>(b, out, N);
}